// round 13
// baseline (speedup 1.0000x reference)
#include <cuda_runtime.h>
#include <math.h>

#define L 512
#define NCON 20
#define INV_TEMP (1.0f / 0.07f)
#define SD_BLOCKS 740   // 5 blocks/SM on 148 SMs (max residency at 48 regs)
#define SD_THREADS 256
#define WPB (SD_THREADS / 32)

// scratch (device globals; no allocation allowed)
__device__ float g_ebar[2][L];           // mean concept embedding per branch
__device__ unsigned int g_mask[2];       // exclusion bitmasks per branch
__device__ float g_pB[SD_BLOCKS];        // per-block partials
__device__ unsigned int g_fin = 0;       // finalize counter (reset by last block)

// ---------------------------------------------------------------------------
// Kernel 1: parallel ebar build. 8 blocks x 128 threads; blocks 0-3 handle
// branch 0 (components b*128..), blocks 4-7 branch 1. One component per
// thread: 5 independent loads + 1 store (~latency-parallel, ~1us).
// Block 0 thread 0 also writes masks and resets the finalize counter.
// ---------------------------------------------------------------------------
__global__ void ebar_kernel(const float* __restrict__ all_emb,
                            const int* __restrict__ Psz, int nPsz,
                            const int* __restrict__ Pnsz, int nPnsz) {
    int b = blockIdx.x;
    int branch = (b >= 4) ? 1 : 0;
    int t = (branch ? (b - 4) : b) * 128 + threadIdx.x;  // 0..511
    const int* P = branch ? Pnsz : Psz;
    int nP = branch ? nPnsz : nPsz;

    float s = 0.0f;
#pragma unroll 5
    for (int j = 0; j < nP; j++) s += all_emb[P[j] * L + t];
    g_ebar[branch][t] = s / (float)nP;

    if (b == 0 && threadIdx.x == 0) {
        unsigned int m0 = 0u, m1 = 0u;
        for (int j = 0; j < nPsz; j++)  m0 |= 1u << Psz[j];
        for (int j = 0; j < nPnsz; j++) m1 |= 1u << Pnsz[j];
        g_mask[0] = m0;
        g_mask[1] = m1;
        g_fin = 0u;
    }
}

// ---------------------------------------------------------------------------
// Kernel 2: sample-driven, TWO samples per warp iteration (proven R12 body),
// NO prolog: ebar read via L1-hot global loads, mask from g_mask.
// Blocks [0,Bs) -> sz samples, [Bs,grid) -> nsz samples.
//   term_i = (log den_i - <row_i, ebar> * invnorm_i / tau) / Nbranch
// Deterministic: fixed per-warp sample sets, fixed-tree reductions,
// fixed-order last-block finalize.
// ---------------------------------------------------------------------------
__global__ void __launch_bounds__(SD_THREADS)
sample_kernel(const float* __restrict__ hg,
              const float* __restrict__ corr,
              const int* __restrict__ sz_idx, int Ns,
              const int* __restrict__ nsz_idx, int Nn,
              int Bs, float invNs, float invNn,
              float* __restrict__ out) {
    __shared__ float sw[WPB];
    __shared__ float sh[SD_THREADS];
    __shared__ bool is_last;

    int tid = threadIdx.x;
    int branch = (blockIdx.x >= Bs) ? 1 : 0;
    const int* idxp = branch ? nsz_idx : sz_idx;
    int count = branch ? Nn : Ns;
    float scale = branch ? invNn : invNs;
    unsigned int mask = g_mask[branch];

    int lane = tid & 31;
    int wib  = tid >> 5;
    int bb = branch ? (blockIdx.x - Bs) : blockIdx.x;
    int nbb = branch ? (gridDim.x - Bs) : Bs;
    int wg = bb * WPB + wib;     // warp index within branch
    int nw = nbb * WPB;          // warps in branch
    int stride = 2 * nw;

    const float4* ep = reinterpret_cast<const float4*>(g_ebar[branch]);
    bool act = lane < NCON;
    float wm = (act && !((mask >> lane) & 1u)) ? 1.0f : 0.0f;

    float acc = 0.0f;
    int i0 = 2 * wg;
    int ra = (i0 < count) ? idxp[i0] : 0;
    int rb = (i0 + 1 < count) ? idxp[i0 + 1] : ra;

    for (int i = i0; i < count; i += stride) {
        bool hasb = (i + 1 < count);
        // prefetch next pair's indices
        int na = (i + stride < count) ? idxp[i + stride] : 0;
        int nb = (i + stride + 1 < count) ? idxp[i + stride + 1] : na;

        // denominators: lanes 0..19 handle one concept each
        float ea = act ? __expf(corr[ra * NCON + lane] * INV_TEMP) : 0.0f;
        float eb = act ? __expf(corr[rb * NCON + lane] * INV_TEMP) : 0.0f;
        float dena = ea * wm;
        float denb = eb * wm;

        const float4* rpa = reinterpret_cast<const float4*>(hg + (size_t)ra * L);
        const float4* rpb = reinterpret_cast<const float4*>(hg + (size_t)rb * L);
        float ssa = 0.0f, da = 0.0f, ssb = 0.0f, db = 0.0f;
#pragma unroll
        for (int it = 0; it < 4; it++) {
            int idx = it * 32 + lane;
            float4 va = rpa[idx];
            float4 vb = rpb[idx];
            float4 ev = ep[idx];
            ssa = fmaf(va.x, va.x, fmaf(va.y, va.y, fmaf(va.z, va.z, fmaf(va.w, va.w, ssa))));
            da  = fmaf(va.x, ev.x, fmaf(va.y, ev.y, fmaf(va.z, ev.z, fmaf(va.w, ev.w, da))));
            ssb = fmaf(vb.x, vb.x, fmaf(vb.y, vb.y, fmaf(vb.z, vb.z, fmaf(vb.w, vb.w, ssb))));
            db  = fmaf(vb.x, ev.x, fmaf(vb.y, ev.y, fmaf(vb.z, ev.z, fmaf(vb.w, ev.w, db))));
        }
#pragma unroll
        for (int o = 16; o > 0; o >>= 1) {
            ssa  += __shfl_xor_sync(0xffffffffu, ssa, o);
            da   += __shfl_xor_sync(0xffffffffu, da, o);
            dena += __shfl_xor_sync(0xffffffffu, dena, o);
            ssb  += __shfl_xor_sync(0xffffffffu, ssb, o);
            db   += __shfl_xor_sync(0xffffffffu, db, o);
            denb += __shfl_xor_sync(0xffffffffu, denb, o);
        }
        if (lane == 0) {
            float invna = 1.0f / fmaxf(sqrtf(ssa), 1e-12f);
            acc += (__logf(dena) - da * invna * INV_TEMP) * scale;
            if (hasb) {
                float invnb = 1.0f / fmaxf(sqrtf(ssb), 1e-12f);
                acc += (__logf(denb) - db * invnb * INV_TEMP) * scale;
            }
        }
        ra = na;
        rb = nb;
    }

    // block partial + last-block fixed-order finalize
    if (lane == 0) sw[wib] = acc;
    __syncthreads();
    if (tid == 0) {
        float s = 0.0f;
#pragma unroll
        for (int k = 0; k < WPB; k++) s += sw[k];
        g_pB[blockIdx.x] = s;
        __threadfence();
        is_last = (atomicAdd(&g_fin, 1u) == gridDim.x - 1);
    }
    __syncthreads();

    if (is_last) {
        __threadfence();  // see all blocks' partials
        float a = 0.0f;
        for (int j = tid; j < SD_BLOCKS; j += SD_THREADS) a += g_pB[j];  // fixed order
        sh[tid] = a;
        __syncthreads();
        for (int s = 128; s > 0; s >>= 1) {
            if (tid < s) sh[tid] += sh[tid + s];
            __syncthreads();
        }
        if (tid == 0) out[0] = sh[0];
    }
}

extern "C" void kernel_launch(void* const* d_in, const int* in_sizes, int n_in,
                              void* d_out, int out_size) {
    const float* hg       = (const float*)d_in[0];
    const float* corr     = (const float*)d_in[1];
    const float* all_emb  = (const float*)d_in[2];
    const int*   sz_idx   = (const int*)d_in[3];
    const int*   nsz_idx  = (const int*)d_in[4];
    const int*   Psz_idx  = (const int*)d_in[5];
    const int*   Pnsz_idx = (const int*)d_in[6];
    float* out = (float*)d_out;

    int Ns    = in_sizes[3];
    int Nn    = in_sizes[4];
    int nPsz  = in_sizes[5];
    int nPnsz = in_sizes[6];

    ebar_kernel<<<8, 128>>>(all_emb, Psz_idx, nPsz, Pnsz_idx, nPnsz);

    // split blocks proportionally between branches
    long long tot = (long long)Ns + (long long)Nn;
    int Bs = (int)(((long long)SD_BLOCKS * Ns + tot - 1) / tot);
    if (Bs < 1) Bs = 1;
    if (Bs > SD_BLOCKS - 1) Bs = SD_BLOCKS - 1;

    sample_kernel<<<SD_BLOCKS, SD_THREADS>>>(hg, corr,
                                             sz_idx, Ns, nsz_idx, Nn,
                                             Bs, 1.0f / (float)Ns, 1.0f / (float)Nn,
                                             out);
}

// round 14
// speedup vs baseline: 1.0802x; 1.0802x over previous
#include <cuda_runtime.h>
#include <math.h>

#define L 512
#define NCON 20
#define INV_TEMP (1.0f / 0.07f)
#define SD_BLOCKS 592   // 4 blocks/SM on 148 SMs (proven residency)
#define SD_THREADS 256
#define WPB (SD_THREADS / 32)

// scratch (device globals; no allocation allowed)
__device__ float g_pB[SD_BLOCKS];        // per-block partials
__device__ unsigned int g_fin = 0;       // finalize counter (reset by last block)

// ---------------------------------------------------------------------------
// Single sample-driven kernel, 8 LANES PER SAMPLE (4 samples per warp).
// Blocks [0,Bs) handle sz samples, [Bs,grid) nsz (branch uniform per block ->
// one smem ebar + one mask). Per sample group (8 lanes):
//   - row loads: 16 iterations x float4, 8 lanes = 128B/line, coalesced
//   - den: 20 concepts spread 3-per-lane (masked), exp on MUFU
//   - 3-stage segmented butterfly (ss, d, den) within the 8-lane group
//   term_i = (log den_i - <row_i, ebar> * invnorm_i / tau) / Nbranch
// Deterministic: fixed per-warp sample sets, fixed-order loop, fixed trees,
// fixed-order last-block finalize.
// ---------------------------------------------------------------------------
__global__ void __launch_bounds__(SD_THREADS)
sample_kernel(const float* __restrict__ hg,
              const float* __restrict__ corr,
              const float* __restrict__ all_emb,
              const int* __restrict__ Psz, int nPsz,
              const int* __restrict__ Pnsz, int nPnsz,
              const int* __restrict__ sz_idx, int Ns,
              const int* __restrict__ nsz_idx, int Nn,
              int Bs, float invNs, float invNn,
              float* __restrict__ out) {
    __shared__ float se[L];
    __shared__ int sp[16];
    __shared__ float sw[WPB];
    __shared__ float sh[SD_THREADS];
    __shared__ bool is_last;

    int tid = threadIdx.x;
    int branch = (blockIdx.x >= Bs) ? 1 : 0;
    const int* P = branch ? Pnsz : Psz;
    int nP = branch ? nPnsz : nPsz;
    const int* idxp = branch ? nsz_idx : sz_idx;
    int count = branch ? Nn : Ns;
    float scale = branch ? invNn : invNs;

    if (tid < nP) sp[tid] = P[tid];
    __syncthreads();

    // exclusion bitmask for this branch (uniform)
    unsigned int mask = 0u;
    for (int j = 0; j < nP; j++) mask |= 1u << sp[j];

    // build this branch's ebar into smem (nP L2-hot concept rows)
    for (int t = tid; t < L; t += SD_THREADS) {
        float s = 0.0f;
        for (int j = 0; j < nP; j++) s += all_emb[sp[j] * L + t];
        se[t] = s / (float)nP;
    }
    __syncthreads();

    int lane  = tid & 31;
    int wib   = tid >> 5;
    int group = lane >> 3;    // 0..3: which sample within the warp's quad
    int lane8 = lane & 7;     // 0..7: lane within the sample group

    int bb  = branch ? (blockIdx.x - Bs) : blockIdx.x;
    int nbb = branch ? (gridDim.x - Bs) : Bs;
    int wg  = bb * WPB + wib;     // warp index within branch
    int nw  = nbb * WPB;          // warps in branch

    const float4* ep = reinterpret_cast<const float4*>(se);

    // concept assignment: lane8 handles c, c+8, (c+16 if < NCON)
    bool c3v = (lane8 + 16) < NCON;
    float wm1 = (!((mask >> lane8) & 1u)) ? 1.0f : 0.0f;
    float wm2 = (!((mask >> (lane8 + 8)) & 1u)) ? 1.0f : 0.0f;
    float wm3 = (c3v && !((mask >> (lane8 + 16)) & 1u)) ? 1.0f : 0.0f;

    float acc = 0.0f;
    for (int base = wg * 4; base < count; base += 4 * nw) {
        int i = base + group;
        bool valid = (i < count);
        int r = valid ? idxp[i] : 0;

        // denominator partials: 3 concepts per lane (masked)
        const float* cr = corr + (size_t)r * NCON;
        float e1 = __expf(cr[lane8] * INV_TEMP);
        float e2 = __expf(cr[lane8 + 8] * INV_TEMP);
        float e3 = c3v ? __expf(cr[lane8 + 16] * INV_TEMP) : 0.0f;
        float den = fmaf(e1, wm1, fmaf(e2, wm2, e3 * wm3));

        // row dot + sumsq: 8 lanes x 16 float4 = 2KB, coalesced per group
        const float4* rp = reinterpret_cast<const float4*>(hg + (size_t)r * L);
        float ss = 0.0f, d = 0.0f;
#pragma unroll 8
        for (int it = 0; it < 16; it++) {
            int idx = it * 8 + lane8;
            float4 v  = rp[idx];
            float4 ev = ep[idx];
            ss = fmaf(v.x, v.x, fmaf(v.y, v.y, fmaf(v.z, v.z, fmaf(v.w, v.w, ss))));
            d  = fmaf(v.x, ev.x, fmaf(v.y, ev.y, fmaf(v.z, ev.z, fmaf(v.w, ev.w, d))));
        }

        // 3-stage segmented butterfly within the 8-lane group
#pragma unroll
        for (int o = 4; o > 0; o >>= 1) {
            ss  += __shfl_xor_sync(0xffffffffu, ss, o);
            d   += __shfl_xor_sync(0xffffffffu, d, o);
            den += __shfl_xor_sync(0xffffffffu, den, o);
        }

        if (lane8 == 0 && valid) {
            float invn = 1.0f / fmaxf(sqrtf(ss), 1e-12f);
            acc += (__logf(den) - d * invn * INV_TEMP) * scale;
        }
    }

    // gather the 4 group accs (lanes 0,8,16,24) into lane 0: offsets 16, 8
    acc += __shfl_xor_sync(0xffffffffu, acc, 16);
    acc += __shfl_xor_sync(0xffffffffu, acc, 8);

    // block partial + last-block fixed-order finalize
    if (lane == 0) sw[wib] = acc;
    __syncthreads();
    if (tid == 0) {
        float s = 0.0f;
#pragma unroll
        for (int k = 0; k < WPB; k++) s += sw[k];
        g_pB[blockIdx.x] = s;
        __threadfence();
        is_last = (atomicAdd(&g_fin, 1u) == gridDim.x - 1);
    }
    __syncthreads();

    if (is_last) {
        __threadfence();  // see all blocks' partials
        float a = 0.0f;
        for (int j = tid; j < SD_BLOCKS; j += SD_THREADS) a += g_pB[j];  // fixed order
        sh[tid] = a;
        __syncthreads();
        for (int s = 128; s > 0; s >>= 1) {
            if (tid < s) sh[tid] += sh[tid + s];
            __syncthreads();
        }
        if (tid == 0) { out[0] = sh[0]; g_fin = 0u; }
    }
}

extern "C" void kernel_launch(void* const* d_in, const int* in_sizes, int n_in,
                              void* d_out, int out_size) {
    const float* hg       = (const float*)d_in[0];
    const float* corr     = (const float*)d_in[1];
    const float* all_emb  = (const float*)d_in[2];
    const int*   sz_idx   = (const int*)d_in[3];
    const int*   nsz_idx  = (const int*)d_in[4];
    const int*   Psz_idx  = (const int*)d_in[5];
    const int*   Pnsz_idx = (const int*)d_in[6];
    float* out = (float*)d_out;

    int Ns    = in_sizes[3];
    int Nn    = in_sizes[4];
    int nPsz  = in_sizes[5];
    int nPnsz = in_sizes[6];

    // split blocks proportionally between branches
    long long tot = (long long)Ns + (long long)Nn;
    int Bs = (int)(((long long)SD_BLOCKS * Ns + tot - 1) / tot);
    if (Bs < 1) Bs = 1;
    if (Bs > SD_BLOCKS - 1) Bs = SD_BLOCKS - 1;

    sample_kernel<<<SD_BLOCKS, SD_THREADS>>>(hg, corr, all_emb,
                                             Psz_idx, nPsz, Pnsz_idx, nPnsz,
                                             sz_idx, Ns, nsz_idx, Nn,
                                             Bs, 1.0f / (float)Ns, 1.0f / (float)Nn,
                                             out);
}